// round 13
// baseline (speedup 1.0000x reference)
#include <cuda_runtime.h>
#include <cuda_fp16.h>

// FFM layer: out[b] = sigmoid( linear(b) + 0.5*sum_k((sum_g f)^2 - sum_g f^2) )
// f[b,g,k] = sum_d dense_x[b,d]*v[d,g,k] + sum_i v[idx[b,i],g,k]
//
// Inputs: d_in[0] dense_x f32[B,13], d_in[1] sparse_x i32[B,26],
//         d_in[2] W f32[26013], d_in[3] b f32[1], d_in[4] v f32[26013,39,8]
// Output: f32 [B]
//
// R13: R12 structure (prep: v->fp16 table + dense_f rows; main: pure 27-row
// fp16 gather-add at the LTS cap). Fix: the dense matvec was LDS-crossbar
// bound (~12us) because each warp streamed all 16KB of v[:13] per SAMPLE.
// Now 4 samples per warp: each smem float4 feeds 4 accumulator sets -> LDS
// traffic /4, leaving the ~4-6us FMA-issue floor.

namespace {
constexpr int N_DENSE  = 13;
constexpr int N_SPARSE = 26;
constexpr int ONEHOT   = 1000;
constexpr int FIELDS   = 39;
constexpr int ROWF     = FIELDS * 8;                   // 312 floats per row
constexpr int ROWH4    = FIELDS;                       // 39 uint4 per fp16 row
constexpr int ROW4     = ROWF / 4;                     // 78 float4 per fp32 row
constexpr int N_ROWS   = N_DENSE + N_SPARSE * ONEHOT;  // 26013
constexpr int TOT      = N_ROWS * ROWF;                // 8,116,056 halves
constexpr int B_MAX    = 16384;
constexpr int SPB      = 8;                            // main: warps per block
constexpr int THREADS  = 256;

constexpr int DSPW       = 4;                          // dense samples/warp
constexpr int DSPB       = 8 * DSPW;                   // 32 samples/block
constexpr int CVT_N      = TOT / 8;                    // uint4 outputs
constexpr int CVT_BLOCKS = (CVT_N + 255) / 256;        // 3964
}

__device__ __align__(16) __half g_vh[TOT];             // 16.2 MB fp16 table
__device__ __align__(16) __half g_df[B_MAX * ROWF];    // 10.2 MB dense_f rows

__device__ __forceinline__ __half2 u2h2(unsigned u) {
    __half2 h; *reinterpret_cast<unsigned*>(&h) = u; return h;
}
__device__ __forceinline__ uint4 pack8(const float* f) {
    __half2 h0 = __floats2half2_rn(f[0], f[1]);
    __half2 h1 = __floats2half2_rn(f[2], f[3]);
    __half2 h2 = __floats2half2_rn(f[4], f[5]);
    __half2 h3 = __floats2half2_rn(f[6], f[7]);
    uint4 o;
    o.x = *reinterpret_cast<unsigned*>(&h0);
    o.y = *reinterpret_cast<unsigned*>(&h1);
    o.z = *reinterpret_cast<unsigned*>(&h2);
    o.w = *reinterpret_cast<unsigned*>(&h3);
    return o;
}

// ---------------------------------------------------------------- prep -----
// Blocks [0, CVT_BLOCKS): convert v fp32 -> fp16 table.
// Blocks [CVT_BLOCKS, ..): dense_f matvec, FOUR samples per warp.
__global__ void __launch_bounds__(THREADS) prep_kernel(
    const float4* __restrict__ v4,
    const float*  __restrict__ dense_x,
    int B)
{
    if (blockIdx.x < CVT_BLOCKS) {
        int i = blockIdx.x * THREADS + threadIdx.x;
        if (i >= CVT_N) return;
        float4 a = __ldg(v4 + 2 * i);
        float4 b = __ldg(v4 + 2 * i + 1);
        float fa[8] = {a.x, a.y, a.z, a.w, b.x, b.y, b.z, b.w};
        reinterpret_cast<uint4*>(g_vh)[i] = pack8(fa);
        return;
    }

    // ---- dense_f: 32 samples per block, 4 per warp ----
    __shared__ float4 s_vd[N_DENSE * ROW4];            // v[:13] fp32, swizzled
    const int tid  = threadIdx.x;
    const int lane = tid & 31;
    const int base = (blockIdx.x - CVT_BLOCKS) * DSPB + (tid >> 5) * DSPW;

    #pragma unroll
    for (int j = tid; j < N_DENSE * ROW4; j += THREADS) {
        int s = j % ROW4;
        int phys = s ^ ((s >> 3) & 1);
        s_vd[(j / ROW4) * ROW4 + phys] = __ldg(v4 + j);
    }
    __syncthreads();
    if (base >= B) return;

    float dx[DSPW];
    #pragma unroll
    for (int s = 0; s < DSPW; ++s) {
        int b = base + s;
        dx[s] = (b < B && lane < N_DENSE) ? dense_x[b * N_DENSE + lane] : 0.0f;
    }
    const bool hasB = (lane < FIELDS - 32);            // lane < 7

    const int jA0 = 2 * lane,      jA1 = 2 * lane + 1;
    const int jB0 = 64 + 2 * lane, jB1 = 65 + 2 * lane;
    const int pA0 = jA0 ^ ((jA0 >> 3) & 1), pA1 = jA1 ^ ((jA1 >> 3) & 1);
    const int pB0 = jB0 ^ ((jB0 >> 3) & 1), pB1 = jB1 ^ ((jB1 >> 3) & 1);

    float fA[DSPW][8], fB[DSPW][8];
    #pragma unroll
    for (int s = 0; s < DSPW; ++s)
        #pragma unroll
        for (int k = 0; k < 8; ++k) { fA[s][k] = 0.0f; fB[s][k] = 0.0f; }

    #pragma unroll
    for (int d = 0; d < N_DENSE; ++d) {
        float xd[DSPW];
        #pragma unroll
        for (int s = 0; s < DSPW; ++s)
            xd[s] = __shfl_sync(0xffffffffu, dx[s], d);

        const float4* row = &s_vd[d * ROW4];
        float4 t0 = row[pA0], t1 = row[pA1];
        #pragma unroll
        for (int s = 0; s < DSPW; ++s) {
            fA[s][0] = fmaf(xd[s], t0.x, fA[s][0]);
            fA[s][1] = fmaf(xd[s], t0.y, fA[s][1]);
            fA[s][2] = fmaf(xd[s], t0.z, fA[s][2]);
            fA[s][3] = fmaf(xd[s], t0.w, fA[s][3]);
            fA[s][4] = fmaf(xd[s], t1.x, fA[s][4]);
            fA[s][5] = fmaf(xd[s], t1.y, fA[s][5]);
            fA[s][6] = fmaf(xd[s], t1.z, fA[s][6]);
            fA[s][7] = fmaf(xd[s], t1.w, fA[s][7]);
        }
        if (hasB) {
            float4 t2 = row[pB0], t3 = row[pB1];
            #pragma unroll
            for (int s = 0; s < DSPW; ++s) {
                fB[s][0] = fmaf(xd[s], t2.x, fB[s][0]);
                fB[s][1] = fmaf(xd[s], t2.y, fB[s][1]);
                fB[s][2] = fmaf(xd[s], t2.z, fB[s][2]);
                fB[s][3] = fmaf(xd[s], t2.w, fB[s][3]);
                fB[s][4] = fmaf(xd[s], t3.x, fB[s][4]);
                fB[s][5] = fmaf(xd[s], t3.y, fB[s][5]);
                fB[s][6] = fmaf(xd[s], t3.z, fB[s][6]);
                fB[s][7] = fmaf(xd[s], t3.w, fB[s][7]);
            }
        }
    }

    #pragma unroll
    for (int s = 0; s < DSPW; ++s) {
        int b = base + s;
        if (b >= B) break;
        uint4* out4 = reinterpret_cast<uint4*>(g_df) + (size_t)b * ROWH4;
        out4[lane] = pack8(fA[s]);
        if (hasB) out4[32 + lane] = pack8(fB[s]);
    }
}

// ---------------------------------------------------------------- main -----
__global__ __launch_bounds__(THREADS) void ffm_kernel(
    const float* __restrict__ dense_x,
    const int*   __restrict__ sparse_x,
    const float* __restrict__ W,
    const float* __restrict__ bias,
    float*       __restrict__ out,
    int B)
{
    const int tid  = threadIdx.x;
    const int lane = tid & 31;
    const int b    = blockIdx.x * SPB + (tid >> 5);
    const bool valid = (b < B);
    const bool hasB  = (lane < FIELDS - 32);           // lane < 7

    float dxr  = (valid && lane < N_DENSE) ? dense_x[b * N_DENSE + lane] : 0.0f;
    int   idxr = (valid && lane < N_SPARSE)
               ? (N_DENSE + lane * ONEHOT + sparse_x[b * N_SPARSE + lane])
               : N_DENSE;

    // Two alternating half2 accumulation chains per field.
    __half2 cA[2][4], cB[2][4];
    #pragma unroll
    for (int c = 0; c < 2; ++c)
        #pragma unroll
        for (int m = 0; m < 4; ++m) {
            cA[c][m] = __floats2half2_rn(0.0f, 0.0f);
            cB[c][m] = __floats2half2_rn(0.0f, 0.0f);
        }

    // Row 0: precomputed dense_f (same layout as a gather row).
    {
        const uint4* dr = reinterpret_cast<const uint4*>(g_df)
                        + (size_t)(valid ? b : 0) * ROWH4;
        uint4 hA = __ldg(dr + lane);
        cA[0][0] = u2h2(hA.x); cA[0][1] = u2h2(hA.y);
        cA[0][2] = u2h2(hA.z); cA[0][3] = u2h2(hA.w);
        if (hasB) {
            uint4 hB = __ldg(dr + 32 + lane);
            cB[0][0] = u2h2(hB.x); cB[0][1] = u2h2(hB.y);
            cB[0][2] = u2h2(hB.z); cB[0][3] = u2h2(hB.w);
        }
    }

    // Rows 1..26: sparse gathers.
    const uint4* vh4 = reinterpret_cast<const uint4*>(g_vh);
    #pragma unroll
    for (int i = 0; i < N_SPARSE; ++i) {
        const int r = __shfl_sync(0xffffffffu, idxr, i);
        const uint4* rp = vh4 + (size_t)r * ROWH4;
        const int c = i & 1;
        uint4 hA = __ldg(rp + lane);
        cA[c][0] = __hadd2(cA[c][0], u2h2(hA.x));
        cA[c][1] = __hadd2(cA[c][1], u2h2(hA.y));
        cA[c][2] = __hadd2(cA[c][2], u2h2(hA.z));
        cA[c][3] = __hadd2(cA[c][3], u2h2(hA.w));
        if (hasB) {
            uint4 hB = __ldg(rp + 32 + lane);
            cB[c][0] = __hadd2(cB[c][0], u2h2(hB.x));
            cB[c][1] = __hadd2(cB[c][1], u2h2(hB.y));
            cB[c][2] = __hadd2(cB[c][2], u2h2(hB.z));
            cB[c][3] = __hadd2(cB[c][3], u2h2(hB.w));
        }
    }

    // Merge chains to fp32 per-field vectors.
    float fA[8], fB[8];
    #pragma unroll
    for (int m = 0; m < 4; ++m) {
        float2 a0 = __half22float2(cA[0][m]);
        float2 a1 = __half22float2(cA[1][m]);
        fA[2 * m]     = a0.x + a1.x;
        fA[2 * m + 1] = a0.y + a1.y;
        float2 b0 = __half22float2(cB[0][m]);
        float2 b1 = __half22float2(cB[1][m]);
        fB[2 * m]     = b0.x + b1.x;
        fB[2 * m + 1] = b0.y + b1.y;
    }

    // Epilogue (fp32).
    float s[8], q = 0.0f;
    #pragma unroll
    for (int k = 0; k < 8; ++k) {
        s[k] = fA[k] + fB[k];
        q = fmaf(fA[k], fA[k], q);
        q = fmaf(fB[k], fB[k], q);
    }

    float lin = 0.0f;
    if (lane < N_SPARSE) lin = __ldg(W + idxr);
    if (lane < N_DENSE)  lin = fmaf(dxr, __ldg(W + lane), lin);

    #pragma unroll
    for (int m = 16; m >= 1; m >>= 1) {
        q   += __shfl_xor_sync(0xffffffffu, q, m);
        lin += __shfl_xor_sync(0xffffffffu, lin, m);
    }
    #pragma unroll
    for (int k = 0; k < 8; ++k)
        #pragma unroll
        for (int m = 16; m >= 1; m >>= 1)
            s[k] += __shfl_xor_sync(0xffffffffu, s[k], m);

    float ss = 0.0f;
    #pragma unroll
    for (int k = 0; k < 8; ++k) ss = fmaf(s[k], s[k], ss);

    if (lane == 0 && valid) {
        float z = lin + 0.5f * (ss - q) + __ldg(bias);
        out[b] = 1.0f / (1.0f + expf(-z));
    }
}

extern "C" void kernel_launch(void* const* d_in, const int* in_sizes, int n_in,
                              void* d_out, int out_size)
{
    const float* dense_x  = (const float*)d_in[0];
    const int*   sparse_x = (const int*)  d_in[1];
    const float* W        = (const float*)d_in[2];
    const float* bias     = (const float*)d_in[3];
    const float* v        = (const float*)d_in[4];
    float*       out      = (float*)d_out;

    const int B = in_sizes[0] / N_DENSE;
    const int dense_blocks = (B + DSPB - 1) / DSPB;

    prep_kernel<<<CVT_BLOCKS + dense_blocks, THREADS>>>(
        reinterpret_cast<const float4*>(v), dense_x, B);

    ffm_kernel<<<(B + SPB - 1) / SPB, THREADS>>>(
        dense_x, sparse_x, W, bias, out, B);
}

// round 14
// speedup vs baseline: 1.1406x; 1.1406x over previous
#include <cuda_runtime.h>
#include <cuda_fp16.h>

// FFM layer: out[b] = sigmoid( linear(b) + 0.5*sum_k((sum_g f)^2 - sum_g f^2) )
// f[b,g,k] = sum_d dense_x[b,d]*v[d,g,k] + sum_i v[idx[b,i],g,k]
//
// Inputs: d_in[0] dense_x f32[B,13], d_in[1] sparse_x i32[B,26],
//         d_in[2] W f32[26013], d_in[3] b f32[1], d_in[4] v f32[26013,39,8]
// Output: f32 [B]
//
// R14: main kernel = R12's 27-row fp16 gather-add (near LTS cap, ~25.6us).
// Prep rewritten: dense matvec in SAMPLE-PER-THREAD layout (thread b loops
// over 39 field chunks with acc[8]+x[13] live -> ~35 regs, no spill; v[:13]
// read as uniform LDS.128 broadcasts). R13's 4-samples/warp tile spilled.

namespace {
constexpr int N_DENSE  = 13;
constexpr int N_SPARSE = 26;
constexpr int ONEHOT   = 1000;
constexpr int FIELDS   = 39;
constexpr int ROWF     = FIELDS * 8;                   // 312 floats per row
constexpr int ROWH4    = FIELDS;                       // 39 uint4 per fp16 row
constexpr int N_ROWS   = N_DENSE + N_SPARSE * ONEHOT;  // 26013
constexpr int TOT      = N_ROWS * ROWF;                // 8,116,056 halves
constexpr int B_MAX    = 16384;

constexpr int SPB      = 8;                            // main: warps per block
constexpr int MTHREADS = 256;

constexpr int PTHREADS   = 128;                        // prep block size
constexpr int CVT_N      = TOT / 8;                    // uint4 outputs
constexpr int CVT_BLOCKS = (CVT_N + PTHREADS - 1) / PTHREADS;  // 7927
constexpr int DSPB       = PTHREADS;                   // dense samples/block
}

__device__ __align__(16) __half g_vh[TOT];             // 16.2 MB fp16 table
__device__ __align__(16) __half g_df[B_MAX * ROWF];    // 10.2 MB dense_f rows

__device__ __forceinline__ __half2 u2h2(unsigned u) {
    __half2 h; *reinterpret_cast<unsigned*>(&h) = u; return h;
}
__device__ __forceinline__ uint4 pack8(const float* f) {
    __half2 h0 = __floats2half2_rn(f[0], f[1]);
    __half2 h1 = __floats2half2_rn(f[2], f[3]);
    __half2 h2 = __floats2half2_rn(f[4], f[5]);
    __half2 h3 = __floats2half2_rn(f[6], f[7]);
    uint4 o;
    o.x = *reinterpret_cast<unsigned*>(&h0);
    o.y = *reinterpret_cast<unsigned*>(&h1);
    o.z = *reinterpret_cast<unsigned*>(&h2);
    o.w = *reinterpret_cast<unsigned*>(&h3);
    return o;
}

// ---------------------------------------------------------------- prep -----
// Blocks [0, CVT_BLOCKS): convert v fp32 -> fp16 table (memory-bound).
// Blocks [CVT_BLOCKS, ..): dense_f matvec, ONE SAMPLE PER THREAD.
__global__ void __launch_bounds__(PTHREADS) prep_kernel(
    const float4* __restrict__ v4,
    const float*  __restrict__ dense_x,
    int B)
{
    if (blockIdx.x < CVT_BLOCKS) {
        int i = blockIdx.x * PTHREADS + threadIdx.x;
        if (i >= CVT_N) return;
        float4 a = __ldg(v4 + 2 * i);
        float4 b = __ldg(v4 + 2 * i + 1);
        float fa[8] = {a.x, a.y, a.z, a.w, b.x, b.y, b.z, b.w};
        reinterpret_cast<uint4*>(g_vh)[i] = pack8(fa);
        return;
    }

    // ---- dense_f: thread = sample ----
    __shared__ float4 s_v[N_DENSE * ROWF / 4];         // v[:13], 16224 B, linear
    __shared__ float  s_x[DSPB * N_DENSE];             // 128 samples' dense_x

    const int tid  = threadIdx.x;
    const int base = (blockIdx.x - CVT_BLOCKS) * DSPB;
    const int b    = base + tid;

    #pragma unroll
    for (int j = tid; j < N_DENSE * ROWF / 4; j += PTHREADS)
        s_v[j] = __ldg(v4 + j);
    for (int j = tid; j < DSPB * N_DENSE; j += PTHREADS) {
        int bb = base + j / N_DENSE;
        s_x[j] = (bb < B) ? dense_x[(size_t)bb * N_DENSE + (j % N_DENSE)] : 0.0f;
    }
    __syncthreads();
    if (b >= B) return;

    float x[N_DENSE];
    #pragma unroll
    for (int d = 0; d < N_DENSE; ++d)
        x[d] = s_x[tid * N_DENSE + d];   // t*13+d mod 32: conflict-free

    uint4* out4 = reinterpret_cast<uint4*>(g_df) + (size_t)b * ROWH4;
    const float4* sv = s_v;

    #pragma unroll 1
    for (int g = 0; g < FIELDS; ++g) {
        float acc[8] = {0,0,0,0,0,0,0,0};
        #pragma unroll
        for (int d = 0; d < N_DENSE; ++d) {
            // uniform broadcast LDS.128 (all lanes same address)
            float4 t0 = sv[(d * FIELDS + g) * 2];
            float4 t1 = sv[(d * FIELDS + g) * 2 + 1];
            acc[0] = fmaf(x[d], t0.x, acc[0]);
            acc[1] = fmaf(x[d], t0.y, acc[1]);
            acc[2] = fmaf(x[d], t0.z, acc[2]);
            acc[3] = fmaf(x[d], t0.w, acc[3]);
            acc[4] = fmaf(x[d], t1.x, acc[4]);
            acc[5] = fmaf(x[d], t1.y, acc[5]);
            acc[6] = fmaf(x[d], t1.z, acc[6]);
            acc[7] = fmaf(x[d], t1.w, acc[7]);
        }
        out4[g] = pack8(acc);
    }
}

// ---------------------------------------------------------------- main -----
__global__ __launch_bounds__(MTHREADS) void ffm_kernel(
    const float* __restrict__ dense_x,
    const int*   __restrict__ sparse_x,
    const float* __restrict__ W,
    const float* __restrict__ bias,
    float*       __restrict__ out,
    int B)
{
    const int tid  = threadIdx.x;
    const int lane = tid & 31;
    const int b    = blockIdx.x * SPB + (tid >> 5);
    const bool valid = (b < B);
    const bool hasB  = (lane < FIELDS - 32);           // lane < 7

    float dxr  = (valid && lane < N_DENSE) ? dense_x[b * N_DENSE + lane] : 0.0f;
    int   idxr = (valid && lane < N_SPARSE)
               ? (N_DENSE + lane * ONEHOT + sparse_x[b * N_SPARSE + lane])
               : N_DENSE;

    // Two alternating half2 accumulation chains per field.
    __half2 cA[2][4], cB[2][4];
    #pragma unroll
    for (int c = 0; c < 2; ++c)
        #pragma unroll
        for (int m = 0; m < 4; ++m) {
            cA[c][m] = __floats2half2_rn(0.0f, 0.0f);
            cB[c][m] = __floats2half2_rn(0.0f, 0.0f);
        }

    // Row 0: precomputed dense_f (same layout as a gather row).
    {
        const uint4* dr = reinterpret_cast<const uint4*>(g_df)
                        + (size_t)(valid ? b : 0) * ROWH4;
        uint4 hA = __ldg(dr + lane);
        cA[0][0] = u2h2(hA.x); cA[0][1] = u2h2(hA.y);
        cA[0][2] = u2h2(hA.z); cA[0][3] = u2h2(hA.w);
        if (hasB) {
            uint4 hB = __ldg(dr + 32 + lane);
            cB[0][0] = u2h2(hB.x); cB[0][1] = u2h2(hB.y);
            cB[0][2] = u2h2(hB.z); cB[0][3] = u2h2(hB.w);
        }
    }

    // Rows 1..26: sparse gathers.
    const uint4* vh4 = reinterpret_cast<const uint4*>(g_vh);
    #pragma unroll
    for (int i = 0; i < N_SPARSE; ++i) {
        const int r = __shfl_sync(0xffffffffu, idxr, i);
        const uint4* rp = vh4 + (size_t)r * ROWH4;
        const int c = i & 1;
        uint4 hA = __ldg(rp + lane);
        cA[c][0] = __hadd2(cA[c][0], u2h2(hA.x));
        cA[c][1] = __hadd2(cA[c][1], u2h2(hA.y));
        cA[c][2] = __hadd2(cA[c][2], u2h2(hA.z));
        cA[c][3] = __hadd2(cA[c][3], u2h2(hA.w));
        if (hasB) {
            uint4 hB = __ldg(rp + 32 + lane);
            cB[c][0] = __hadd2(cB[c][0], u2h2(hB.x));
            cB[c][1] = __hadd2(cB[c][1], u2h2(hB.y));
            cB[c][2] = __hadd2(cB[c][2], u2h2(hB.z));
            cB[c][3] = __hadd2(cB[c][3], u2h2(hB.w));
        }
    }

    // Merge chains to fp32 per-field vectors.
    float fA[8], fB[8];
    #pragma unroll
    for (int m = 0; m < 4; ++m) {
        float2 a0 = __half22float2(cA[0][m]);
        float2 a1 = __half22float2(cA[1][m]);
        fA[2 * m]     = a0.x + a1.x;
        fA[2 * m + 1] = a0.y + a1.y;
        float2 b0 = __half22float2(cB[0][m]);
        float2 b1 = __half22float2(cB[1][m]);
        fB[2 * m]     = b0.x + b1.x;
        fB[2 * m + 1] = b0.y + b1.y;
    }

    // Epilogue (fp32).
    float s[8], q = 0.0f;
    #pragma unroll
    for (int k = 0; k < 8; ++k) {
        s[k] = fA[k] + fB[k];
        q = fmaf(fA[k], fA[k], q);
        q = fmaf(fB[k], fB[k], q);
    }

    float lin = 0.0f;
    if (lane < N_SPARSE) lin = __ldg(W + idxr);
    if (lane < N_DENSE)  lin = fmaf(dxr, __ldg(W + lane), lin);

    #pragma unroll
    for (int m = 16; m >= 1; m >>= 1) {
        q   += __shfl_xor_sync(0xffffffffu, q, m);
        lin += __shfl_xor_sync(0xffffffffu, lin, m);
    }
    #pragma unroll
    for (int k = 0; k < 8; ++k)
        #pragma unroll
        for (int m = 16; m >= 1; m >>= 1)
            s[k] += __shfl_xor_sync(0xffffffffu, s[k], m);

    float ss = 0.0f;
    #pragma unroll
    for (int k = 0; k < 8; ++k) ss = fmaf(s[k], s[k], ss);

    if (lane == 0 && valid) {
        float z = lin + 0.5f * (ss - q) + __ldg(bias);
        out[b] = 1.0f / (1.0f + expf(-z));
    }
}

extern "C" void kernel_launch(void* const* d_in, const int* in_sizes, int n_in,
                              void* d_out, int out_size)
{
    const float* dense_x  = (const float*)d_in[0];
    const int*   sparse_x = (const int*)  d_in[1];
    const float* W        = (const float*)d_in[2];
    const float* bias     = (const float*)d_in[3];
    const float* v        = (const float*)d_in[4];
    float*       out      = (float*)d_out;

    const int B = in_sizes[0] / N_DENSE;
    const int dense_blocks = (B + DSPB - 1) / DSPB;

    prep_kernel<<<CVT_BLOCKS + dense_blocks, PTHREADS>>>(
        reinterpret_cast<const float4*>(v), dense_x, B);

    ffm_kernel<<<(B + SPB - 1) / SPB, MTHREADS>>>(
        dense_x, sparse_x, W, bias, out, B);
}